// round 15
// baseline (speedup 1.0000x reference)
#include <cuda_runtime.h>

// ChamferLoss, B=4, N=M=8192, 3D — SINGLE kernel.
// Pair phase: R10 config (THREADS=128, IPT=16, JT=64) at the fp32 wide-fma
// floor. Mins combined via global atomicMax on mapped key 0x7f800000-bits(d)
// (zero-init == +inf, so no init kernel; max == min). Last finishing block
// (atomic counter, deadlock-free at any occupancy) reduces the 256KB L2-hot
// min buffers, writes out[0] deterministically, and resets state for replay.

#define BB 4
#define NPTS 8192
#define MPTS 8192
#define THREADS 128
#define IPT 16
#define KKN (IPT / 2)
#define ITILES (NPTS / (THREADS * IPT))   // 4
#define JT 64
#define JCH (MPTS / JT)                   // 128
#define G 8
#define NBLOCKS (ITILES * JT * BB)        // 1024
#define TOTPTS (BB * NPTS)                // 32768 per side

typedef unsigned long long u64;

__device__ int g_m1[TOTPTS];   // mapped row mins (zero-init == +inf)
__device__ int g_m2[TOTPTS];   // mapped col mins
__device__ unsigned g_count = 0;

#define PACK2(o, lo, hi)   asm("mov.b64 %0,{%1,%2};" : "=l"(o) : "f"(lo), "f"(hi))
#define UNPACK2(lo, hi, i) asm("mov.b64 {%0,%1},%2;" : "=f"(lo), "=f"(hi) : "l"(i))
#define FMA2(d, a, b, c)   asm("fma.rn.f32x2 %0,%1,%2,%3;" : "=l"(d) : "l"(a), "l"(b), "l"(c))
#define ADD2(d, a, b)      asm("add.rn.f32x2 %0,%1,%2;" : "=l"(d) : "l"(a), "l"(b))

#define MAPK 0x7f800000

__global__ void __launch_bounds__(THREADS) chamfer_fused_kernel(
    const float* __restrict__ xyz1, const float* __restrict__ xyz2, float* __restrict__ out)
{
    __shared__ ulonglong2 tA[JCH];
    __shared__ ulonglong2 tB[JCH];
    __shared__ float sred[4];

    const int tid = threadIdx.x;
    const int lane = tid & 31;
    const int warp = tid >> 5;
    const int b = blockIdx.z;
    const int iBase = blockIdx.x * (THREADS * IPT);
    const int jBase = blockIdx.y * JCH;
    const float* __restrict__ P = xyz1 + (size_t)b * NPTS * 3;
    const float* __restrict__ Q = xyz2 + (size_t)b * MPTS * 3;

    // ---------------- pair phase (R10 core, unchanged) ----------------
    u64 ax2[KKN], ay2[KKN], az2[KKN], n12[KKN];
    float mn[IPT];
#pragma unroll
    for (int kk = 0; kk < KKN; kk++) {
        int i0 = iBase + tid + (2 * kk) * THREADS;
        int i1 = iBase + tid + (2 * kk + 1) * THREADS;
        float x0 = P[i0 * 3], y0 = P[i0 * 3 + 1], z0 = P[i0 * 3 + 2];
        float x1 = P[i1 * 3], y1 = P[i1 * 3 + 1], z1 = P[i1 * 3 + 2];
        PACK2(ax2[kk], x0, x1);
        PACK2(ay2[kk], y0, y1);
        PACK2(az2[kk], z0, z1);
        float n0 = fmaf(x0, x0, fmaf(y0, y0, z0 * z0));
        float n1 = fmaf(x1, x1, fmaf(y1, y1, z1 * z1));
        PACK2(n12[kk], n0, n1);
        mn[2 * kk] = 3.4e38f;
        mn[2 * kk + 1] = 3.4e38f;
    }

    for (int jj = tid; jj < JCH; jj += THREADS) {
        int j = jBase + jj;
        float x = Q[j * 3], y = Q[j * 3 + 1], z = Q[j * 3 + 2];
        float n2 = fmaf(x, x, fmaf(y, y, z * z));
        float nx = -2.f * x, ny = -2.f * y, nz = -2.f * z;
        u64 X2, Y2, Z2, W2;
        PACK2(X2, nx, nx);
        PACK2(Y2, ny, ny);
        PACK2(Z2, nz, nz);
        PACK2(W2, n2, n2);
        tA[jj] = make_ulonglong2(X2, Y2);
        tB[jj] = make_ulonglong2(Z2, W2);
    }
    __syncthreads();

    int* __restrict__ colDst = g_m2 + b * MPTS + jBase;

    for (int jj0 = 0; jj0 < JCH; jj0 += G) {
        int cvi[G];
#pragma unroll
        for (int g = 0; g < G; g++) {
            ulonglong2 ba = tA[jj0 + g];
            ulonglong2 bb = tB[jj0 + g];
            float c0 = 3.4e38f, c1 = 3.4e38f;
#pragma unroll
            for (int kk = 0; kk < KKN; kk++) {
                u64 w, t;
                ADD2(w, n12[kk], bb.y);        // n1 + n2
                FMA2(t, bb.x, az2[kk], w);     // += -2z*az
                FMA2(t, ba.y, ay2[kk], t);     // += -2y*ay
                FMA2(t, ba.x, ax2[kk], t);     // += -2x*ax -> dist^2 x2
                float t0, t1;
                UNPACK2(t0, t1, t);
                mn[2 * kk]     = fminf(mn[2 * kk], t0);
                mn[2 * kk + 1] = fminf(mn[2 * kk + 1], t1);
                c0 = fminf(c0, t0);
                c1 = fminf(c1, t1);
            }
            cvi[g] = __float_as_int(fmaxf(fminf(c0, c1), 0.f));  // clamp -> s32 order
        }
#pragma unroll
        for (int g = 0; g < G; g++)
            cvi[g] = __reduce_min_sync(0xffffffffu, cvi[g]);
        int myv = cvi[0];
#pragma unroll
        for (int g = 1; g < G; g++)
            if (lane == g) myv = cvi[g];
        if (lane < G)
            atomicMax(&colDst[jj0 + lane], MAPK - myv);   // mapped: max == min
    }

    // Row mins: spread-address atomicMax (result unused -> REDG).
    int* __restrict__ rowDst = g_m1 + b * NPTS;
#pragma unroll
    for (int kk = 0; kk < KKN; kk++) {
        int i0 = iBase + tid + (2 * kk) * THREADS;
        int i1 = iBase + tid + (2 * kk + 1) * THREADS;
        int k0 = MAPK - __float_as_int(fmaxf(mn[2 * kk], 0.f));
        int k1 = MAPK - __float_as_int(fmaxf(mn[2 * kk + 1], 0.f));
        atomicMax(&rowDst[i0], k0);
        atomicMax(&rowDst[i1], k1);
    }

    // ---------------- last-block final reduce ----------------
    __threadfence();
    __syncthreads();
    __shared__ bool isLast;
    if (tid == 0)
        isLast = (atomicAdd(&g_count, 1u) == NBLOCKS - 1);
    __syncthreads();
    if (!isLast) return;

    // This block is the last to finish: all atomicMax results are visible
    // (L2-serialized atomics + threadfence). Buffers never touched our L1.
    float s = 0.f;
    const int4* m1 = (const int4*)g_m1;
    const int4* m2 = (const int4*)g_m2;
    for (int k = tid; k < TOTPTS / 4; k += THREADS) {
        int4 a = m1[k];
        int4 c = m2[k];
        s += __int_as_float(MAPK - a.x) + __int_as_float(MAPK - a.y)
           + __int_as_float(MAPK - a.z) + __int_as_float(MAPK - a.w);
        s += __int_as_float(MAPK - c.x) + __int_as_float(MAPK - c.y)
           + __int_as_float(MAPK - c.z) + __int_as_float(MAPK - c.w);
    }
    s *= (1.f / TOTPTS);
#pragma unroll
    for (int o = 16; o > 0; o >>= 1) s += __shfl_down_sync(0xffffffffu, s, o);
    if (lane == 0) sred[warp] = s;
    __syncthreads();
    if (tid == 0) {
        out[0] = (sred[0] + sred[1]) + (sred[2] + sred[3]);
        g_count = 0;                       // reset for next graph replay
    }
    __syncthreads();
    // Zero the min buffers for the next replay (zero == mapped +inf).
    int4 z4 = make_int4(0, 0, 0, 0);
    for (int k = tid; k < TOTPTS / 4; k += THREADS) {
        ((int4*)g_m1)[k] = z4;
        ((int4*)g_m2)[k] = z4;
    }
}

extern "C" void kernel_launch(void* const* d_in, const int* in_sizes, int n_in,
                              void* d_out, int out_size) {
    const float* xyz1 = (const float*)d_in[0];
    const float* xyz2 = (const float*)d_in[1];
    float* out = (float*)d_out;

    dim3 grid(ITILES, JT, BB);  // (4, 64, 4) = 1024 blocks
    chamfer_fused_kernel<<<grid, THREADS>>>(xyz1, xyz2, out);
}